// round 1
// baseline (speedup 1.0000x reference)
#include <cuda_runtime.h>
#include <cstdint>

#define S_LEN   2048
#define D_K     64
#define BH      64
#define MT      64          // q-tile rows per block
#define NT      64          // k-tile cols per iteration
#define PAD     72          // smem row stride (floats) — conflict-free mma gathers
#define THREADS 256

__device__ __forceinline__ uint32_t f2tf32(float x) {
    uint32_t r;
    asm("cvt.rna.tf32.f32 %0, %1;" : "=r"(r) : "f"(x));
    return r;
}

__device__ __forceinline__ void mma_tf32(float c[4],
                                         uint32_t a0, uint32_t a1, uint32_t a2, uint32_t a3,
                                         uint32_t b0, uint32_t b1) {
    asm volatile(
        "mma.sync.aligned.m16n8k8.row.col.f32.tf32.tf32.f32 "
        "{%0,%1,%2,%3},{%4,%5,%6,%7},{%8,%9},{%0,%1,%2,%3};"
        : "+f"(c[0]), "+f"(c[1]), "+f"(c[2]), "+f"(c[3])
        : "r"(a0), "r"(a1), "r"(a2), "r"(a3), "r"(b0), "r"(b1));
}

// Load a 64x64 fp32 tile (contiguous in gmem) into smem with PAD stride,
// scaling and rounding to tf32.
__device__ __forceinline__ void load_tile_tf32(float* dst, const float* __restrict__ src,
                                               int tid, float scale) {
    const float4* s4 = (const float4*)src;
    #pragma unroll
    for (int i = 0; i < 4; i++) {
        int idx = i * THREADS + tid;          // 1024 float4s total
        float4 v = s4[idx];
        int row = idx >> 4;                   // 16 float4 per row
        int c4  = (idx & 15) << 2;
        float* d = dst + row * PAD + c4;
        d[0] = __uint_as_float(f2tf32(v.x * scale));
        d[1] = __uint_as_float(f2tf32(v.y * scale));
        d[2] = __uint_as_float(f2tf32(v.z * scale));
        d[3] = __uint_as_float(f2tf32(v.w * scale));
    }
}

__global__ __launch_bounds__(THREADS)
void sdpa_kernel(const float* __restrict__ Q, const float* __restrict__ K,
                 const float* __restrict__ V, const int* __restrict__ mask,
                 float* __restrict__ out) {
    extern __shared__ float sm[];
    float* Qs = sm;                 // MT x PAD
    float* Ks = Qs + MT * PAD;      // NT x PAD
    float* Vs = Ks + NT * PAD;      // NT x PAD
    float* Ss = Vs + NT * PAD;      // MT x PAD  (scores, then P)

    const int bh  = blockIdx.y;
    const int q0  = blockIdx.x * MT;
    const int tid = threadIdx.x;
    const int lane = tid & 31, wid = tid >> 5;
    const int g = lane >> 2, tig = lane & 3;
    const int wm = wid & 3, wn = wid >> 2;     // 4 warps in M, 2 in N

    const float* Qg = Q + ((size_t)bh * S_LEN + q0) * D_K;
    const float* Kg = K + (size_t)bh * S_LEN * D_K;
    const float* Vg = V + (size_t)bh * S_LEN * D_K;
    const int*   Mg = mask + (size_t)bh * S_LEN * S_LEN;
    float* ctx  = out + (size_t)bh * S_LEN * D_K;
    float* attn = out + (size_t)BH * S_LEN * D_K + (size_t)bh * S_LEN * S_LEN;

    // Q tile: scale by 1/sqrt(64) = 0.125 folded in, converted to tf32
    load_tile_tf32(Qs, Qg, tid, 0.125f);

    // softmax stats: thread (tid) owns row sr with 3 replicas (4 lanes/row)
    const int sr = tid >> 2;       // 0..63
    const int sp = tid & 3;        // 16-col slice within the tile row
    float m_run = -INFINITY, l_run = 0.f;

    // ---------------- phase 1: score stats (no stores) ----------------
    for (int kt = 0; kt < S_LEN; kt += NT) {
        __syncthreads();
        load_tile_tf32(Ks, Kg + (size_t)kt * D_K, tid, 1.0f);
        __syncthreads();

        float acc[4][4] = {};
        #pragma unroll
        for (int k0 = 0; k0 < D_K; k0 += 8) {
            uint32_t a0 = __float_as_uint(Qs[(wm*16 + g    ) * PAD + k0 + tig    ]);
            uint32_t a1 = __float_as_uint(Qs[(wm*16 + g + 8) * PAD + k0 + tig    ]);
            uint32_t a2 = __float_as_uint(Qs[(wm*16 + g    ) * PAD + k0 + tig + 4]);
            uint32_t a3 = __float_as_uint(Qs[(wm*16 + g + 8) * PAD + k0 + tig + 4]);
            #pragma unroll
            for (int nf = 0; nf < 4; nf++) {
                int nc = wn*32 + nf*8 + g;
                uint32_t b0 = __float_as_uint(Ks[nc * PAD + k0 + tig    ]);
                uint32_t b1 = __float_as_uint(Ks[nc * PAD + k0 + tig + 4]);
                mma_tf32(acc[nf], a0, a1, a2, a3, b0, b1);
            }
        }
        // stage score tile to smem
        #pragma unroll
        for (int nf = 0; nf < 4; nf++) {
            int col = wn*32 + nf*8 + 2*tig;
            Ss[(wm*16 + g    ) * PAD + col    ] = acc[nf][0];
            Ss[(wm*16 + g    ) * PAD + col + 1] = acc[nf][1];
            Ss[(wm*16 + g + 8) * PAD + col    ] = acc[nf][2];
            Ss[(wm*16 + g + 8) * PAD + col + 1] = acc[nf][3];
        }
        __syncthreads();

        // online (m, l) update over this tile's 16-col slice
        {
            const int4* mrow = (const int4*)(Mg + (size_t)(q0 + sr) * S_LEN + kt + sp*16);
            const float* srow = Ss + sr * PAD + sp * 16;
            float v[16];
            float mx = -INFINITY;
            #pragma unroll
            for (int j = 0; j < 4; j++) {
                int4 mk = mrow[j];
                v[4*j+0] = mk.x ? srow[4*j+0] : -1e9f;
                v[4*j+1] = mk.y ? srow[4*j+1] : -1e9f;
                v[4*j+2] = mk.z ? srow[4*j+2] : -1e9f;
                v[4*j+3] = mk.w ? srow[4*j+3] : -1e9f;
                mx = fmaxf(mx, fmaxf(fmaxf(v[4*j], v[4*j+1]), fmaxf(v[4*j+2], v[4*j+3])));
            }
            mx = fmaxf(mx, __shfl_xor_sync(0xffffffffu, mx, 1));
            mx = fmaxf(mx, __shfl_xor_sync(0xffffffffu, mx, 2));
            float m_new = fmaxf(m_run, mx);
            float s = 0.f;
            #pragma unroll
            for (int j = 0; j < 16; j++) s += __expf(v[j] - m_new);
            s += __shfl_xor_sync(0xffffffffu, s, 1);
            s += __shfl_xor_sync(0xffffffffu, s, 2);
            l_run = l_run * __expf(m_run - m_new) + s;
            m_run = m_new;
        }
    }
    const float l_inv = 1.f / l_run;

    // ---------------- phase 2: recompute, write attn, accumulate P.V ----------------
    float o[4][4] = {};
    for (int kt = 0; kt < S_LEN; kt += NT) {
        __syncthreads();
        load_tile_tf32(Ks, Kg + (size_t)kt * D_K, tid, 1.0f);
        load_tile_tf32(Vs, Vg + (size_t)kt * D_K, tid, 1.0f);
        __syncthreads();

        float acc[4][4] = {};
        #pragma unroll
        for (int k0 = 0; k0 < D_K; k0 += 8) {
            uint32_t a0 = __float_as_uint(Qs[(wm*16 + g    ) * PAD + k0 + tig    ]);
            uint32_t a1 = __float_as_uint(Qs[(wm*16 + g + 8) * PAD + k0 + tig    ]);
            uint32_t a2 = __float_as_uint(Qs[(wm*16 + g    ) * PAD + k0 + tig + 4]);
            uint32_t a3 = __float_as_uint(Qs[(wm*16 + g + 8) * PAD + k0 + tig + 4]);
            #pragma unroll
            for (int nf = 0; nf < 4; nf++) {
                int nc = wn*32 + nf*8 + g;
                uint32_t b0 = __float_as_uint(Ks[nc * PAD + k0 + tig    ]);
                uint32_t b1 = __float_as_uint(Ks[nc * PAD + k0 + tig + 4]);
                mma_tf32(acc[nf], a0, a1, a2, a3, b0, b1);
            }
        }
        #pragma unroll
        for (int nf = 0; nf < 4; nf++) {
            int col = wn*32 + nf*8 + 2*tig;
            Ss[(wm*16 + g    ) * PAD + col    ] = acc[nf][0];
            Ss[(wm*16 + g    ) * PAD + col + 1] = acc[nf][1];
            Ss[(wm*16 + g + 8) * PAD + col    ] = acc[nf][2];
            Ss[(wm*16 + g + 8) * PAD + col + 1] = acc[nf][3];
        }
        __syncthreads();

        // p = exp(s_masked - m) / l ; write to attn gmem and Ps (in-place in Ss)
        {
            const int4* mrow = (const int4*)(Mg + (size_t)(q0 + sr) * S_LEN + kt + sp*16);
            float* srow = Ss + sr * PAD + sp * 16;
            float4* arow = (float4*)(attn + (size_t)(q0 + sr) * S_LEN + kt + sp*16);
            #pragma unroll
            for (int j = 0; j < 4; j++) {
                int4 mk = mrow[j];
                float v0 = mk.x ? srow[4*j+0] : -1e9f;
                float v1 = mk.y ? srow[4*j+1] : -1e9f;
                float v2 = mk.z ? srow[4*j+2] : -1e9f;
                float v3 = mk.w ? srow[4*j+3] : -1e9f;
                float4 p;
                p.x = __expf(v0 - m_run) * l_inv;
                p.y = __expf(v1 - m_run) * l_inv;
                p.z = __expf(v2 - m_run) * l_inv;
                p.w = __expf(v3 - m_run) * l_inv;
                srow[4*j+0] = p.x; srow[4*j+1] = p.y;
                srow[4*j+2] = p.z; srow[4*j+3] = p.w;
                arow[j] = p;
            }
        }
        __syncthreads();

        // O += P (MT x NT) @ V (NT x D_K)
        #pragma unroll
        for (int kk = 0; kk < NT; kk += 8) {
            uint32_t a0 = f2tf32(Ss[(wm*16 + g    ) * PAD + kk + tig    ]);
            uint32_t a1 = f2tf32(Ss[(wm*16 + g + 8) * PAD + kk + tig    ]);
            uint32_t a2 = f2tf32(Ss[(wm*16 + g    ) * PAD + kk + tig + 4]);
            uint32_t a3 = f2tf32(Ss[(wm*16 + g + 8) * PAD + kk + tig + 4]);
            #pragma unroll
            for (int nf = 0; nf < 4; nf++) {
                int dc = wn*32 + nf*8 + g;
                uint32_t b0 = __float_as_uint(Vs[(kk + tig    ) * PAD + dc]);
                uint32_t b1 = __float_as_uint(Vs[(kk + tig + 4) * PAD + dc]);
                mma_tf32(o[nf], a0, a1, a2, a3, b0, b1);
            }
        }
    }

    // write context
    #pragma unroll
    for (int nf = 0; nf < 4; nf++) {
        int col = wn*32 + nf*8 + 2*tig;
        float* c0 = ctx + (size_t)(q0 + wm*16 + g    ) * D_K + col;
        float* c1 = ctx + (size_t)(q0 + wm*16 + g + 8) * D_K + col;
        c0[0] = o[nf][0]; c0[1] = o[nf][1];
        c1[0] = o[nf][2]; c1[1] = o[nf][3];
    }
}

extern "C" void kernel_launch(void* const* d_in, const int* in_sizes, int n_in,
                              void* d_out, int out_size) {
    const float* Q    = (const float*)d_in[0];
    const float* K    = (const float*)d_in[1];
    const float* V    = (const float*)d_in[2];
    const int*   mask = (const int*)d_in[3];
    float* out = (float*)d_out;

    const int smem_bytes = (MT + 3 * NT) * PAD * sizeof(float);  // 4 * 64 * 72 * 4 = 73728
    cudaFuncSetAttribute(sdpa_kernel, cudaFuncAttributeMaxDynamicSharedMemorySize, smem_bytes);

    dim3 grid(S_LEN / MT, BH);   // (32, 64)
    sdpa_kernel<<<grid, THREADS, smem_bytes>>>(Q, K, V, mask, out);
}

// round 2
// speedup vs baseline: 1.4657x; 1.4657x over previous
#include <cuda_runtime.h>
#include <cstdint>

#define S_LEN   2048
#define D_K     64
#define BH      64
#define MT      64
#define NT      64
#define PADK    68          // stride%32banks = 4 -> conflict-free K/P gathers
#define PADV    72          // stride%32banks = 8 -> conflict-free V B-operand gathers
#define THREADS 256

__device__ float g_linv[BH * S_LEN];   // 512 KB scratch (static, allowed)

__device__ __forceinline__ uint32_t f2tf32(float x) {
    uint32_t r;
    asm("cvt.rna.tf32.f32 %0, %1;" : "=r"(r) : "f"(x));
    return r;
}

__device__ __forceinline__ void mma_tf32(float c[4],
                                         uint32_t a0, uint32_t a1, uint32_t a2, uint32_t a3,
                                         uint32_t b0, uint32_t b1) {
    asm volatile(
        "mma.sync.aligned.m16n8k8.row.col.f32.tf32.tf32.f32 "
        "{%0,%1,%2,%3},{%4,%5,%6,%7},{%8,%9},{%0,%1,%2,%3};"
        : "+f"(c[0]), "+f"(c[1]), "+f"(c[2]), "+f"(c[3])
        : "r"(a0), "r"(a1), "r"(a2), "r"(a3), "r"(b0), "r"(b1));
}

// 64x64 fp32 tile gmem->smem with pad stride, tf32-rounded
__device__ __forceinline__ void load_tile_tf32(float* dst, const float* __restrict__ src,
                                               int tid, int pad) {
    const float4* s4 = (const float4*)src;
    #pragma unroll
    for (int i = 0; i < 4; i++) {
        int idx = i * THREADS + tid;
        float4 v = s4[idx];
        int row = idx >> 4;
        int c4  = (idx & 15) << 2;
        float* d = dst + row * pad + c4;
        d[0] = __uint_as_float(f2tf32(v.x));
        d[1] = __uint_as_float(f2tf32(v.y));
        d[2] = __uint_as_float(f2tf32(v.z));
        d[3] = __uint_as_float(f2tf32(v.w));
    }
}

__global__ __launch_bounds__(THREADS, 2)
void sdpa_fwd(const float* __restrict__ Q, const float* __restrict__ K,
              const float* __restrict__ V, const int* __restrict__ mask,
              float* __restrict__ out) {
    extern __shared__ float sm[];
    float* Ks   = sm;                    // NT x PADK
    float* Vs   = Ks + NT * PADK;        // NT x PADV
    float* Ps   = Vs + NT * PADV;        // MT x PADK
    float* red  = Ps + MT * PADK;        // 64 x 4 partial row sums
    float* liS  = red + 64 * 4;          // 64 l_inv

    const int bh  = blockIdx.y;
    const int q0  = blockIdx.x * MT;
    const int tid = threadIdx.x;
    const int lane = tid & 31, wid = tid >> 5;
    const int g = lane >> 2, tig = lane & 3;
    const int wm = wid & 1;              // 2 warps in M (32 rows each)
    const int wn = wid >> 1;             // 4 warps in N (16 cols each)

    const float* Qg = Q + ((size_t)bh * S_LEN + q0) * D_K;
    const float* Kg = K + (size_t)bh * S_LEN * D_K;
    const float* Vg = V + (size_t)bh * S_LEN * D_K;
    const int*   Mg = mask + (size_t)bh * S_LEN * S_LEN;
    float* ctx  = out + (size_t)bh * S_LEN * D_K;
    float* attn = out + (size_t)BH * S_LEN * D_K + (size_t)bh * S_LEN * S_LEN;

    // ---- hoist Q fragments into registers (scale 1/8 folded, tf32) ----
    uint32_t qf[8][2][4];
    #pragma unroll
    for (int j = 0; j < 8; j++) {
        #pragma unroll
        for (int mb = 0; mb < 2; mb++) {
            int r0 = wm * 32 + mb * 16 + g;
            const float* p0 = Qg + (size_t)r0 * D_K + j * 8;
            const float* p1 = Qg + (size_t)(r0 + 8) * D_K + j * 8;
            qf[j][mb][0] = f2tf32(p0[tig]     * 0.125f);
            qf[j][mb][1] = f2tf32(p1[tig]     * 0.125f);
            qf[j][mb][2] = f2tf32(p0[tig + 4] * 0.125f);
            qf[j][mb][3] = f2tf32(p1[tig + 4] * 0.125f);
        }
    }

    float o[2][2][4] = {};
    float lp[2][2] = {};                 // row-sum partials [mb][half]

    for (int kt = 0; kt < S_LEN; kt += NT) {
        __syncthreads();                 // prior tile's smem consumers done
        load_tile_tf32(Ks, Kg + (size_t)kt * D_K, tid, PADK);
        load_tile_tf32(Vs, Vg + (size_t)kt * D_K, tid, PADV);
        __syncthreads();

        // ---- S = Q K^T (scaled) ----
        float acc[2][2][4] = {};
        #pragma unroll
        for (int j = 0; j < 8; j++) {
            int k0 = j * 8;
            uint32_t b0[2], b1[2];
            #pragma unroll
            for (int nf = 0; nf < 2; nf++) {
                int nc = wn * 16 + nf * 8 + g;
                b0[nf] = __float_as_uint(Ks[nc * PADK + k0 + tig]);
                b1[nf] = __float_as_uint(Ks[nc * PADK + k0 + tig + 4]);
            }
            #pragma unroll
            for (int mb = 0; mb < 2; mb++)
                #pragma unroll
                for (int nf = 0; nf < 2; nf++)
                    mma_tf32(acc[mb][nf], qf[j][mb][0], qf[j][mb][1],
                             qf[j][mb][2], qf[j][mb][3], b0[nf], b1[nf]);
        }

        // ---- mask + exp in accumulator layout; write attn; stage P ----
        #pragma unroll
        for (int mb = 0; mb < 2; mb++) {
            int row = wm * 32 + mb * 16 + g;       // local q row
            #pragma unroll
            for (int nf = 0; nf < 2; nf++) {
                int col = wn * 16 + nf * 8 + 2 * tig;
                const int2 m0 = *(const int2*)(Mg + (size_t)(q0 + row)     * S_LEN + kt + col);
                const int2 m1 = *(const int2*)(Mg + (size_t)(q0 + row + 8) * S_LEN + kt + col);
                float p00 = m0.x ? __expf(acc[mb][nf][0]) : 0.f;
                float p01 = m0.y ? __expf(acc[mb][nf][1]) : 0.f;
                float p10 = m1.x ? __expf(acc[mb][nf][2]) : 0.f;
                float p11 = m1.y ? __expf(acc[mb][nf][3]) : 0.f;
                lp[mb][0] += p00 + p01;
                lp[mb][1] += p10 + p11;
                // unnormalized attn (fixed up by norm kernel)
                *(float2*)(attn + (size_t)(q0 + row)     * S_LEN + kt + col) = make_float2(p00, p01);
                *(float2*)(attn + (size_t)(q0 + row + 8) * S_LEN + kt + col) = make_float2(p10, p11);
                // stage tf32-rounded P for PV mma
                float2 s0, s1;
                s0.x = __uint_as_float(f2tf32(p00)); s0.y = __uint_as_float(f2tf32(p01));
                s1.x = __uint_as_float(f2tf32(p10)); s1.y = __uint_as_float(f2tf32(p11));
                *(float2*)&Ps[row       * PADK + col] = s0;
                *(float2*)&Ps[(row + 8) * PADK + col] = s1;
            }
        }
        __syncthreads();

        // ---- O += P V ----
        #pragma unroll
        for (int j = 0; j < 8; j++) {
            int kk = j * 8;
            uint32_t a[2][4];
            #pragma unroll
            for (int mb = 0; mb < 2; mb++) {
                int r0 = wm * 32 + mb * 16 + g;
                a[mb][0] = __float_as_uint(Ps[r0       * PADK + kk + tig]);
                a[mb][1] = __float_as_uint(Ps[(r0 + 8) * PADK + kk + tig]);
                a[mb][2] = __float_as_uint(Ps[r0       * PADK + kk + tig + 4]);
                a[mb][3] = __float_as_uint(Ps[(r0 + 8) * PADK + kk + tig + 4]);
            }
            #pragma unroll
            for (int nf = 0; nf < 2; nf++) {
                int dc = wn * 16 + nf * 8 + g;
                uint32_t b0 = __float_as_uint(Vs[(kk + tig)     * PADV + dc]);
                uint32_t b1 = __float_as_uint(Vs[(kk + tig + 4) * PADV + dc]);
                #pragma unroll
                for (int mb = 0; mb < 2; mb++)
                    mma_tf32(o[mb][nf], a[mb][0], a[mb][1], a[mb][2], a[mb][3], b0, b1);
            }
        }
    }

    // ---- row-sum reduction -> l_inv ----
    #pragma unroll
    for (int mb = 0; mb < 2; mb++)
        #pragma unroll
        for (int h = 0; h < 2; h++) {
            float s = lp[mb][h];
            s += __shfl_xor_sync(0xffffffffu, s, 1);
            s += __shfl_xor_sync(0xffffffffu, s, 2);
            lp[mb][h] = s;
        }
    if (tig == 0) {
        #pragma unroll
        for (int mb = 0; mb < 2; mb++)
            #pragma unroll
            for (int h = 0; h < 2; h++)
                red[(wm * 32 + mb * 16 + g + h * 8) * 4 + wn] = lp[mb][h];
    }
    __syncthreads();
    if (tid < 64) {
        float l = red[tid * 4] + red[tid * 4 + 1] + red[tid * 4 + 2] + red[tid * 4 + 3];
        float li = 1.f / l;
        liS[tid] = li;
        g_linv[bh * S_LEN + q0 + tid] = li;
    }
    __syncthreads();

    // ---- scale + write context ----
    #pragma unroll
    for (int mb = 0; mb < 2; mb++) {
        int row = wm * 32 + mb * 16 + g;
        float li0 = liS[row], li1 = liS[row + 8];
        #pragma unroll
        for (int nf = 0; nf < 2; nf++) {
            int col = wn * 16 + nf * 8 + 2 * tig;
            *(float2*)(ctx + (size_t)(q0 + row)     * D_K + col) =
                make_float2(o[mb][nf][0] * li0, o[mb][nf][1] * li0);
            *(float2*)(ctx + (size_t)(q0 + row + 8) * D_K + col) =
                make_float2(o[mb][nf][2] * li1, o[mb][nf][3] * li1);
        }
    }
}

// attn *= 1/l   (pure streaming, ~2.14 GB)
__global__ __launch_bounds__(256)
void norm_attn(float* __restrict__ attn) {
    size_t t = (size_t)blockIdx.x * 256 + threadIdx.x;   // float4 index
    float li = g_linv[t >> 9];                           // 512 float4 per row
    float4* p = (float4*)attn + t;
    float4 v = *p;
    v.x *= li; v.y *= li; v.z *= li; v.w *= li;
    *p = v;
}

extern "C" void kernel_launch(void* const* d_in, const int* in_sizes, int n_in,
                              void* d_out, int out_size) {
    const float* Q    = (const float*)d_in[0];
    const float* K    = (const float*)d_in[1];
    const float* V    = (const float*)d_in[2];
    const int*   mask = (const int*)d_in[3];
    float* out = (float*)d_out;

    const int smem_bytes = (NT * PADK + NT * PADV + MT * PADK + 64 * 4 + 64) * sizeof(float);
    cudaFuncSetAttribute(sdpa_fwd, cudaFuncAttributeMaxDynamicSharedMemorySize, smem_bytes);

    dim3 grid(S_LEN / MT, BH);
    sdpa_fwd<<<grid, THREADS, smem_bytes>>>(Q, K, V, mask, out);

    size_t attn_f4 = (size_t)BH * S_LEN * S_LEN / 4;     // 67,108,864
    norm_attn<<<(unsigned)(attn_f4 / 256), 256>>>(out + (size_t)BH * S_LEN * D_K);
}